// round 4
// baseline (speedup 1.0000x reference)
#include <cuda_runtime.h>
#include <cuda_bf16.h>

// XingLoss: P=16384 rows, N=1024 points (x,y) fp32. segn = N/4 = 256 segments/row.
// Segment i of row p uses points x[p, 3i .. 3i+3]; term depends on
//   c12 = cross(v1,v2)  (sign only -> direct),  sina = cross(v1,v3)/(|v1||v3|)
// out = scale * mean_p( sum_i term / segn )

#define P_ROWS 16384
#define SEGN   256
#define NPTS   1024

__device__ float g_partials[P_ROWS];

__global__ __launch_bounds__(SEGN) void xing_rows_kernel(const float* __restrict__ x) {
    const int p = blockIdx.x;
    const int i = threadIdx.x;  // segment index within row

    // float offset of point (p, 3i): (p*1024 + 3i)*2 -> byte offset 8*(p*1024+3i): 8B aligned
    const float* base = x + (size_t)p * (NPTS * 2) + 6 * i;

    float2 q0 = *reinterpret_cast<const float2*>(base + 0);
    float2 q1 = *reinterpret_cast<const float2*>(base + 2);
    float2 q2 = *reinterpret_cast<const float2*>(base + 4);
    float2 q3 = *reinterpret_cast<const float2*>(base + 6);

    float v1x = q1.x - q0.x, v1y = q1.y - q0.y;
    float v2x = q2.x - q1.x, v2y = q2.y - q1.y;
    float v3x = q3.x - q2.x, v3y = q3.y - q2.y;

    float c12 = v1x * v2y - v1y * v2x;
    float c13 = v1x * v3y - v1y * v3x;
    float d1 = v1x * v1x + v1y * v1y;
    float d3 = v3x * v3x + v3y * v3y;
    float sina = c13 / sqrtf(d1 * d3);

    // direct = (s12 >= 0); sign(s12) == sign(c12) since norms > 0
    float term = (c12 >= 0.0f) ? fmaxf(-sina, 0.0f) : fmaxf(sina, 0.0f);

    // warp reduce
    #pragma unroll
    for (int off = 16; off > 0; off >>= 1)
        term += __shfl_down_sync(0xFFFFFFFFu, term, off);

    __shared__ float warp_sums[SEGN / 32];
    const int lane = i & 31, wid = i >> 5;
    if (lane == 0) warp_sums[wid] = term;
    __syncthreads();

    if (wid == 0) {
        float s = (lane < SEGN / 32) ? warp_sums[lane] : 0.0f;
        #pragma unroll
        for (int off = 4; off > 0; off >>= 1)
            s += __shfl_down_sync(0xFFFFFFFFu, s, off);
        if (lane == 0) g_partials[p] = s;
    }
}

// Decode a scalar of unknown dtype (int32 or fp32). For a plain python int
// (e.g. 1), the raw bits reinterpreted as float are denormal/huge -> use int.
__device__ __forceinline__ float decode_scale(const int* sp) {
    if (sp == nullptr) return 1.0f;
    int bits = *sp;
    float f = __int_as_float(bits);
    float af = fabsf(f);
    if (af > 1e-30f && af < 1e30f) return f;   // plausible float
    return (float)bits;                        // treat as int
}

__global__ __launch_bounds__(256) void xing_reduce_kernel(const int* __restrict__ scale_p,
                                                          float* __restrict__ out) {
    const int t = threadIdx.x;
    double acc = 0.0;
    for (int j = t; j < P_ROWS; j += 256)
        acc += (double)g_partials[j];

    __shared__ double sh[256];
    sh[t] = acc;
    __syncthreads();
    for (int off = 128; off > 0; off >>= 1) {
        if (t < off) sh[t] += sh[t + off];
        __syncthreads();
    }
    if (t == 0) {
        float scale = decode_scale(scale_p);
        // mean over P of (row_sum / SEGN), times scale
        double result = sh[0] / ((double)SEGN * (double)P_ROWS) * (double)scale;
        out[0] = (float)result;
    }
}

extern "C" void kernel_launch(void* const* d_in, const int* in_sizes, int n_in,
                              void* d_out, int out_size) {
    const float* x = (const float*)d_in[0];
    const int* scale_p = (n_in > 1) ? (const int*)d_in[1] : nullptr;
    float* out = (float*)d_out;

    xing_rows_kernel<<<P_ROWS, SEGN>>>(x);
    xing_reduce_kernel<<<1, 256>>>(scale_p, out);
}